// round 16
// baseline (speedup 1.0000x reference)
#include <cuda_runtime.h>
#include <cuda_fp16.h>
#include <math.h>

// Problem constants (fixed by the dataset)
#define NMAX   100000
#define DIM    64
#define Hdim   14     // H = 2*LAT
#define PD     16     // P = (LAT+1)*R
#define LATC   7
#define OUTC   30     // 7 loc + 7 scale + 14 U + 2 m
#define SP_INV_1 0.5413248546129181f
#define CAP    64     // bucket capacity per row; P(deg>64)~1e-30 for Poisson(10)
#define EPT    4      // edges per thread in the scatter (R14 best config)

// ---------------- scratch (static device globals; zero-init at load) -------
// g_cnt is SELF-RESTORING: agg2 zeroes it after reading, so no memset node.
// feature row = 16 fp16 = 32B = 2 x uint4 (16B-aligned for LDG.128)
__device__ uint4  g_Y1h[NMAX * 2];       // X@W1 (fp16, padded 16 feats, pads=0)
__device__ uint4  g_Y2h[NMAX * 2];       // relu(agg1)@W2 (fp16)
__device__ int    g_cnt[NMAX];           // per-row bucket fill count
__device__ int2   g_edge[NMAX * CAP];    // fixed-capacity buckets: (col, val_bits)

// pack 8 fp32 -> uint4 of half2s
__device__ __forceinline__ uint4 pack8h(const float* v) {
    half2 a = __floats2half2_rn(v[0], v[1]);
    half2 b = __floats2half2_rn(v[2], v[3]);
    half2 c = __floats2half2_rn(v[4], v[5]);
    half2 d = __floats2half2_rn(v[6], v[7]);
    uint4 r;
    r.x = *reinterpret_cast<unsigned*>(&a);
    r.y = *reinterpret_cast<unsigned*>(&b);
    r.z = *reinterpret_cast<unsigned*>(&c);
    r.w = *reinterpret_cast<unsigned*>(&d);
    return r;
}
// pack 4 fp32 -> uint2 of half2
__device__ __forceinline__ uint2 pack4h(float a, float b, float c, float d) {
    half2 lo = __floats2half2_rn(a, b);
    half2 hi = __floats2half2_rn(c, d);
    uint2 r;
    r.x = *reinterpret_cast<unsigned*>(&lo);
    r.y = *reinterpret_cast<unsigned*>(&hi);
    return r;
}
// fma 8 halves (uint4) into 8 fp32 accumulators
__device__ __forceinline__ void fma8(float* acc, uint4 r, float v) {
    float2 f;
    f = __half22float2(*reinterpret_cast<half2*>(&r.x)); acc[0] += v * f.x; acc[1] += v * f.y;
    f = __half22float2(*reinterpret_cast<half2*>(&r.y)); acc[2] += v * f.x; acc[3] += v * f.y;
    f = __half22float2(*reinterpret_cast<half2*>(&r.z)); acc[4] += v * f.x; acc[5] += v * f.y;
    f = __half22float2(*reinterpret_cast<half2*>(&r.w)); acc[6] += v * f.x; acc[7] += v * f.y;
}

// ---------------- K_FAT: gemm1 (blocks < gN) || bucket scatter (rest) ------
// R14 config: EPT=4, no launch bounds (reg caps measured harmful 3x).
__global__ void k_fat(const float* __restrict__ X, const float* __restrict__ W1,
                      const int* __restrict__ rows, const int* __restrict__ cols,
                      const float* __restrict__ vals, int N, int E, int gN) {
    if ((int)blockIdx.x >= gN) {
        int base = (blockIdx.x - gN) * (blockDim.x * EPT) + threadIdx.x;
        int r[EPT], c[EPT];
        float v[EPT];
        bool ok[EPT];
#pragma unroll
        for (int u = 0; u < EPT; ++u) {
            int e = base + u * blockDim.x;
            ok[u] = (e < E);
            int es = ok[u] ? e : 0;
            r[u] = __ldg(&rows[es]);
            c[u] = __ldg(&cols[es]);
            v[u] = __ldg(&vals[es]);
        }
        int p[EPT];
#pragma unroll
        for (int u = 0; u < EPT; ++u)
            p[u] = ok[u] ? atomicAdd(&g_cnt[r[u]], 1) : CAP;
#pragma unroll
        for (int u = 0; u < EPT; ++u)
            if (p[u] < CAP)
                g_edge[r[u] * CAP + p[u]] = make_int2(c[u], __float_as_int(v[u]));
        return;
    }

    // gemm part: Y1h = pack(X @ W1)  (N x 64 x 14)
    __shared__ float sW[DIM * Hdim];   // 896 floats
    for (int t = threadIdx.x; t < DIM * Hdim; t += blockDim.x)
        sW[t] = W1[t];
    __syncthreads();

    int i = blockIdx.x * blockDim.x + threadIdx.x;
    if (i >= N) return;

    const float4* x4 = (const float4*)(X + (long)i * DIM);
    float acc[16];
#pragma unroll
    for (int j = 0; j < 16; ++j) acc[j] = 0.f;

#pragma unroll
    for (int k4 = 0; k4 < DIM / 4; ++k4) {
        float4 x = x4[k4];
        const float* w = &sW[k4 * 4 * Hdim];
#pragma unroll
        for (int j = 0; j < Hdim; ++j)
            acc[j] += x.x * w[j] + x.y * w[Hdim + j]
                    + x.z * w[2 * Hdim + j] + x.w * w[3 * Hdim + j];
    }
    acc[14] = 0.f; acc[15] = 0.f;

    g_Y1h[i * 2 + 0] = pack8h(acc);
    g_Y1h[i * 2 + 1] = pack8h(acc + 8);
}

// ---------------- helpers ---------------------------------------------------
__device__ __forceinline__ float ftanh(float x) {
    x = fminf(fmaxf(x, -15.f), 15.f);
    float e = __expf(2.f * x);
    return (e - 1.f) / (e + 1.f);
}
__device__ __forceinline__ float fsoftplus(float x) {
    return log1pf(__expf(x));   // input range ~[-0.46, 1.54]: safe
}

// edge-split aggregation: 4 lanes per node, lane q owns edges q, q+4, ...
// Each edge: 1 x LDG.64 (record) + 2 x LDG.128 (full 32B row) = 3 LSU ops.
// Private acc[16] per lane; quad butterfly at the end gives every lane h[16].
__device__ __forceinline__ void agg_edges(const uint4* __restrict__ src,
                                          int i, int cnt, int q, float* acc) {
    int base = i * CAP;
    int end  = base + cnt;
    int e = base + q;
    if (e < end) {
        int2 ed = __ldg(&g_edge[e]);
        for (;;) {
            int en = e + 4;
            bool more = (en < end);
            int2 edn;
            if (more) edn = __ldg(&g_edge[en]);

            uint4 r0 = __ldg(&src[(long)ed.x * 2 + 0]);
            uint4 r1 = __ldg(&src[(long)ed.x * 2 + 1]);
            float v = __int_as_float(ed.y);
            fma8(acc,     r0, v);
            fma8(acc + 8, r1, v);

            if (!more) break;
            ed = edn; e = en;
        }
    }
    // quad reduction: every lane ends with the full 16-feature sum
#pragma unroll
    for (int d = 0; d < 16; ++d) {
        acc[d] += __shfl_xor_sync(0xffffffffu, acc[d], 1);
        acc[d] += __shfl_xor_sync(0xffffffffu, acc[d], 2);
    }
}

// ---------------- K_AGG1: Y2h = pack(relu(agg(Y1h)) @ W2) ------------------
__global__ void k_agg1(const float* __restrict__ W2, int N) {
    __shared__ float sW[Hdim * 16];    // W2 padded to 14x16, pads = 0
    for (int t = threadIdx.x; t < Hdim * 16; t += blockDim.x) {
        int k = t >> 4, j = t & 15;
        sW[t] = (j < Hdim) ? W2[k * Hdim + j] : 0.f;
    }
    __syncthreads();

    int tid = blockIdx.x * blockDim.x + threadIdx.x;
    int i = tid >> 2, q = tid & 3;
    bool valid = (i < N);
    int ic = valid ? i : 0;

    int c = valid ? min(__ldg(&g_cnt[ic]), CAP) : 0;
    float h[16];
#pragma unroll
    for (int d = 0; d < 16; ++d) h[d] = 0.f;
    agg_edges(g_Y1h, ic, c, q, h);

#pragma unroll
    for (int d = 0; d < 16; ++d) h[d] = fmaxf(h[d], 0.f);

    int j0 = q * 4;
    float y[4] = {0.f, 0.f, 0.f, 0.f};
#pragma unroll
    for (int k = 0; k < Hdim; ++k) {
        float hk = h[k];
#pragma unroll
        for (int d = 0; d < 4; ++d)
            y[d] += hk * sW[k * 16 + j0 + d];
    }

    if (valid)
        ((uint2*)g_Y2h)[(long)i * 4 + q] = pack4h(y[0], y[1], y[2], y[3]);
}

// ---------------- K_AGG2: agg(Y2h) -> relu -> heads -> out (+restore) ------
__global__ void k_agg2(const float* __restrict__ Wd1, const float* __restrict__ bd1,
                       const float* __restrict__ Wd2, const float* __restrict__ bd2,
                       float* __restrict__ out, int N) {
    __shared__ float sW1[Hdim * 16];   // Wd1 padded 14x16
    __shared__ float sW2[Hdim * 16];   // Wd2 14x16 (natural)
    __shared__ float sB1[16];
    __shared__ float sB2[16];
    for (int t = threadIdx.x; t < Hdim * 16; t += blockDim.x) {
        int k = t >> 4, j = t & 15;
        sW1[t] = (j < Hdim) ? Wd1[k * Hdim + j] : 0.f;
        sW2[t] = Wd2[k * PD + j];
    }
    if (threadIdx.x < 16) {
        sB1[threadIdx.x] = (threadIdx.x < Hdim) ? bd1[threadIdx.x] : 0.f;
        sB2[threadIdx.x] = bd2[threadIdx.x];
    }
    __syncthreads();

    int tid = blockIdx.x * blockDim.x + threadIdx.x;
    int i = tid >> 2, q = tid & 3;
    bool valid = (i < N);
    int ic = valid ? i : 0;

    int c = valid ? min(__ldg(&g_cnt[ic]), CAP) : 0;
    float h[16];
#pragma unroll
    for (int d = 0; d < 16; ++d) h[d] = 0.f;
    agg_edges(g_Y2h, ic, c, q, h);

    // self-restore bucket counts for the next call (c already consumed)
    if (valid && q == 0) g_cnt[i] = 0;

#pragma unroll
    for (int d = 0; d < 16; ++d) h[d] = fmaxf(h[d], 0.f);

    int j0 = q * 4;
    float pd[4], pp[4];
#pragma unroll
    for (int d = 0; d < 4; ++d) { pd[d] = sB1[j0 + d]; pp[d] = sB2[j0 + d]; }
#pragma unroll
    for (int k = 0; k < Hdim; ++k) {
        float hk = h[k];
#pragma unroll
        for (int d = 0; d < 4; ++d) {
            pd[d] += hk * sW1[k * 16 + j0 + d];
            pp[d] += hk * sW2[k * 16 + j0 + d];
        }
    }

    if (valid) {
        float* o = out + (long)i * OUTC;
#pragma unroll
        for (int d = 0; d < 4; ++d) {
            int j = j0 + d;
            if (j < Hdim) {
                float t = ftanh(pd[d]);
                o[j] = (j < LATC) ? t : fsoftplus(t + SP_INV_1);
            }
            o[Hdim + j] = ftanh(pp[d]);   // 16 perturb outputs: U(14) + m(2)
        }
    }
}

// ---------------- launch: THREE kernels -------------------------------------
extern "C" void kernel_launch(void* const* d_in, const int* in_sizes, int n_in,
                              void* d_out, int out_size) {
    const float* X    = (const float*)d_in[0];
    const int*   rows = (const int*)d_in[1];
    const int*   cols = (const int*)d_in[2];
    const float* vals = (const float*)d_in[3];
    const float* W1   = (const float*)d_in[4];
    const float* W2   = (const float*)d_in[5];
    const float* Wd1  = (const float*)d_in[6];
    const float* bd1  = (const float*)d_in[7];
    const float* Wd2  = (const float*)d_in[8];
    const float* bd2  = (const float*)d_in[9];
    float* out = (float*)d_out;

    int N = in_sizes[0] / DIM;
    int E = in_sizes[1];

    const int T = 256;
    int gN  = (N + T - 1) / T;
    int gE4 = (E + T * EPT - 1) / (T * EPT);
    int g4N = (N * 4 + T - 1) / T;

    k_fat <<<gN + gE4, T>>>(X, W1, rows, cols, vals, N, E, gN); // gemm || bucket
    k_agg1<<<g4N, T>>>(W2, N);
    k_agg2<<<g4N, T>>>(Wd1, bd1, Wd2, bd2, out, N);
}